// round 1
// baseline (speedup 1.0000x reference)
#include <cuda_runtime.h>
#include <cstdint>

#define NB 256
#define NQ 1000
#define NC 80
#define TOPK 300
#define NPAD 1024
#define THREADS 512

// Monotone float <-> ordered-uint mapping (works for any finite float, incl. -1.0 mask)
__device__ __forceinline__ unsigned f2ord(float f) {
    unsigned u = __float_as_uint(f);
    return (u & 0x80000000u) ? ~u : (u | 0x80000000u);
}
__device__ __forceinline__ float ord2f(unsigned u) {
    return (u & 0x80000000u) ? __uint_as_float(u & 0x7FFFFFFFu)
                             : __uint_as_float(~u);
}

__global__ __launch_bounds__(THREADS)
void rtdetr_post_kernel(const float* __restrict__ logits,
                        const float* __restrict__ pboxes,
                        const float* __restrict__ tsizes,
                        float* __restrict__ out)
{
    __shared__ unsigned long long keys[NPAD];

    const int b    = blockIdx.x;
    const int tid  = threadIdx.x;
    const int wid  = tid >> 5;
    const int lane = tid & 31;

    // ---------------- Phase A: per-query max+argmax over 80 classes ----------
    // Warp per query: 80 contiguous floats read by 32 lanes (coalesced),
    // shfl tree reduction with first-index tie-break (matches jnp.argmax).
    const float* lg = logits + (size_t)b * NQ * NC;
    for (int q = wid; q < NQ; q += THREADS / 32) {
        const float* row = lg + q * NC;
        float v  = row[lane];       int ci = lane;
        float v2 = row[lane + 32];  if (v2 > v) { v = v2; ci = lane + 32; }
        if (lane < 16) { float v3 = row[lane + 64]; if (v3 > v) { v = v3; ci = lane + 64; } }
        #pragma unroll
        for (int off = 16; off; off >>= 1) {
            float ov = __shfl_down_sync(0xffffffffu, v,  off);
            int   oi = __shfl_down_sync(0xffffffffu, ci, off);
            if (ov > v || (ov == v && oi < ci)) { v = ov; ci = oi; }
        }
        if (lane == 0) {
            // sigmoid is monotone: score = sigmoid(max logit)
            float s  = 1.0f / (1.0f + expf(-v));
            float ms = (s > 0.05f) ? s : -1.0f;   // masked score (ref semantics)
            unsigned us = f2ord(ms);
            // key: [score ordered 32b | (1023 - q) 10b | label 10b]
            // (1023-q) gives smaller index => larger key => stable tie-break
            keys[q] = ((unsigned long long)us << 32)
                    | ((unsigned long long)(1023 - q) << 10)
                    | (unsigned)ci;
        }
    }
    if (tid < NPAD - NQ) keys[NQ + tid] = 0ULL;   // padding: minimum key
    __syncthreads();

    // ---------------- Phase B: bitonic sort, descending ----------------------
    for (int k = 2; k <= NPAD; k <<= 1) {
        for (int j = k >> 1; j > 0; j >>= 1) {
            for (int i = tid; i < NPAD; i += THREADS) {
                int l = i ^ j;
                if (l > i) {
                    unsigned long long a = keys[i], c = keys[l];
                    bool up = ((i & k) == 0);     // up-blocks sorted descending
                    if (up ? (a < c) : (a > c)) { keys[i] = c; keys[l] = a; }
                }
            }
            __syncthreads();
        }
    }

    // ---------------- Phase C: emit top-300 ---------------------------------
    const float img_h = tsizes[b * 2 + 0];
    const float img_w = tsizes[b * 2 + 1];
    if (tid < TOPK) {
        unsigned long long key = keys[tid];
        unsigned us = (unsigned)(key >> 32);
        float s     = ord2f(us);
        int   q     = 1023 - (int)((key >> 10) & 0x3FFu);
        int   label = (int)(key & 0x3FFu);
        bool  valid = s > 0.05f;

        int o = b * TOPK + tid;
        out[o]                = valid ? s : 0.0f;                 // scores
        out[NB * TOPK + o]    = valid ? (float)label : -1.0f;     // labels

        float4 r = make_float4(0.f, 0.f, 0.f, 0.f);
        if (valid) {
            float4 pb = *(const float4*)(pboxes + ((size_t)b * NQ + q) * 4);
            r.x = (pb.x - 0.5f * pb.z) * img_w;
            r.y = (pb.y - 0.5f * pb.w) * img_h;
            r.z = (pb.x + 0.5f * pb.z) * img_w;
            r.w = (pb.y + 0.5f * pb.w) * img_h;
        }
        *(float4*)(out + 2 * NB * TOPK + (size_t)o * 4) = r;       // boxes
    }
}

extern "C" void kernel_launch(void* const* d_in, const int* in_sizes, int n_in,
                              void* d_out, int out_size) {
    const float* logits = (const float*)d_in[0];  // (256,1000,80)
    const float* boxes  = (const float*)d_in[1];  // (256,1000,4)
    const float* tsz    = (const float*)d_in[2];  // (256,2)
    float* out = (float*)d_out;                   // scores | labels | boxes, flattened
    rtdetr_post_kernel<<<NB, THREADS>>>(logits, boxes, tsz, out);
}